// round 15
// baseline (speedup 1.0000x reference)
#include <cuda_runtime.h>
#include <cuda_fp16.h>
#include <math.h>
#include <stdint.h>

#define B_   128
#define S_   1000
#define H_   256
#define M_   (B_ * S_)   // 128000

// ---------------- scratch (__device__ globals; no allocation allowed) ----------
__device__ float g_ce[B_ * H_];
__device__ float g_ct[B_ * H_];
__device__ float g_cs[B_ * H_];
__device__ float g_gi[B_ * 3 * H_];       // dec @ Wih^T
__device__ float g_gh[B_ * 3 * H_];       // lasth @ Whh^T
__device__ float g_hnew[B_ * H_];
__device__ float g_scores[2 * M_];        // raw scores -> softmaxed in place
__device__ float g_ctx[2 * B_ * H_];      // enc ctx, tgt ctx
__device__ float g_d[2 * B_ * H_];        // d_e, d_t
// fp16 stacked weights [Wenc1; Wtgt1; Wptr1] cols [0,H)
__device__ __half g_Wh[768 * H_];

// =================== mma.sync / ldmatrix / cp.async helpers ====================
__device__ __forceinline__ uint32_t s2u(const void* p) {
    uint32_t a;
    asm("{ .reg .u64 t; cvta.to.shared.u64 t, %1; cvt.u32.u64 %0, t; }" : "=r"(a) : "l"(p));
    return a;
}
__device__ __forceinline__ void ldsm4(uint32_t& r0, uint32_t& r1, uint32_t& r2, uint32_t& r3,
                                      uint32_t addr) {
    asm volatile("ldmatrix.sync.aligned.m8n8.x4.shared.b16 {%0,%1,%2,%3}, [%4];"
                 : "=r"(r0), "=r"(r1), "=r"(r2), "=r"(r3) : "r"(addr));
}
__device__ __forceinline__ void ldsm2(uint32_t& r0, uint32_t& r1, uint32_t addr) {
    asm volatile("ldmatrix.sync.aligned.m8n8.x2.shared.b16 {%0,%1}, [%2];"
                 : "=r"(r0), "=r"(r1) : "r"(addr));
}
__device__ __forceinline__ void mma16816h(float& d0, float& d1, float& d2, float& d3,
                                          uint32_t a0, uint32_t a1, uint32_t a2, uint32_t a3,
                                          uint32_t b0, uint32_t b1) {
    asm volatile("mma.sync.aligned.m16n8k16.row.col.f32.f16.f16.f32 "
                 "{%0,%1,%2,%3}, {%4,%5,%6,%7}, {%8,%9}, {%0,%1,%2,%3};"
                 : "+f"(d0), "+f"(d1), "+f"(d2), "+f"(d3)
                 : "r"(a0), "r"(a1), "r"(a2), "r"(a3), "r"(b0), "r"(b1));
}
__device__ __forceinline__ void cpa16(uint32_t dst, const void* src) {
    asm volatile("cp.async.cg.shared.global [%0], [%1], 16;" :: "r"(dst), "l"(src));
}
__device__ __forceinline__ void cpa_commit() {
    asm volatile("cp.async.commit_group;" ::: "memory");
}

// ---------------- zero ctx accumulators ----------------------------------------
__global__ void zero_ctx() {
    int i = blockIdx.x * blockDim.x + threadIdx.x;
    if (i < 2 * B_ * H_) g_ctx[i] = 0.0f;
}

// ---------------- prepass: weight fp32 -> fp16 ----------------------------------
__global__ void conv_w(const float* __restrict__ Wenc,
                       const float* __restrict__ Wtgt,
                       const float* __restrict__ Wptr) {
    int g = blockIdx.x * blockDim.x + threadIdx.x;   // 24576 groups of 8
    int row = g >> 5, c8 = g & 31;
    const float* src;
    if (row < 256)      src = Wenc + (size_t)row * (2 * H_) + c8 * 8;
    else if (row < 512) src = Wtgt + (size_t)(row - 256) * (2 * H_) + c8 * 8;
    else                src = Wptr + (size_t)(row - 512) * (3 * H_) + c8 * 8;
    float4 x0 = *(const float4*)src;
    float4 x1 = *(const float4*)(src + 4);
    __half h[8];
    h[0] = __float2half_rn(x0.x); h[1] = __float2half_rn(x0.y);
    h[2] = __float2half_rn(x0.z); h[3] = __float2half_rn(x0.w);
    h[4] = __float2half_rn(x1.x); h[5] = __float2half_rn(x1.y);
    h[6] = __float2half_rn(x1.z); h[7] = __float2half_rn(x1.w);
    *(uint4*)(g_Wh + (size_t)row * H_ + c8 * 8) = *(uint4*)h;
}

// ---------------- small fp32 GEMM: C[M,N] = A[M,256] @ W[N,256]^T ---------------
__device__ __forceinline__ void gemm64_body(const float* __restrict__ A,
                                            const float* __restrict__ W, int wstride,
                                            float* __restrict__ C, int ldc,
                                            int m0, int n0) {
    __shared__ float As[32][64];
    __shared__ float Bs[32][64];
    const int tid = threadIdx.x;
    const int lm = tid & 63;
    const int lq = tid >> 6;
    const int tn = tid & 15;
    const int tm = tid >> 4;

    float acc[4][4];
    #pragma unroll
    for (int i = 0; i < 4; ++i)
        #pragma unroll
        for (int j = 0; j < 4; ++j) acc[i][j] = 0.f;

    const float* arow = A + (size_t)(m0 + lm) * 256;
    const float* wrow = W + (size_t)(n0 + lm) * wstride;

    for (int kt = 0; kt < 8; ++kt) {
        const int k0 = kt * 32;
        #pragma unroll
        for (int h = 0; h < 2; ++h) {
            const int kk = (lq + h * 4) * 4;
            float4 xa = *(const float4*)(arow + k0 + kk);
            As[kk + 0][lm] = xa.x; As[kk + 1][lm] = xa.y;
            As[kk + 2][lm] = xa.z; As[kk + 3][lm] = xa.w;
            float4 wa = *(const float4*)(wrow + k0 + kk);
            Bs[kk + 0][lm] = wa.x; Bs[kk + 1][lm] = wa.y;
            Bs[kk + 2][lm] = wa.z; Bs[kk + 3][lm] = wa.w;
        }
        __syncthreads();
        #pragma unroll
        for (int k = 0; k < 32; ++k) {
            float4 a = *(const float4*)&As[k][tm * 4];
            float4 b = *(const float4*)&Bs[k][tn * 4];
            acc[0][0] += a.x * b.x; acc[0][1] += a.x * b.y; acc[0][2] += a.x * b.z; acc[0][3] += a.x * b.w;
            acc[1][0] += a.y * b.x; acc[1][1] += a.y * b.y; acc[1][2] += a.y * b.z; acc[1][3] += a.y * b.w;
            acc[2][0] += a.z * b.x; acc[2][1] += a.z * b.y; acc[2][2] += a.z * b.z; acc[2][3] += a.z * b.w;
            acc[3][0] += a.w * b.x; acc[3][1] += a.w * b.y; acc[3][2] += a.w * b.z; acc[3][3] += a.w * b.w;
        }
        __syncthreads();
    }
    #pragma unroll
    for (int i = 0; i < 4; ++i) {
        float4 o = make_float4(acc[i][0], acc[i][1], acc[i][2], acc[i][3]);
        *(float4*)(C + (size_t)(m0 + tm * 4 + i) * ldc + n0 + tn * 4) = o;
    }
}

// merged small GEMMs: z=0: gi, z=1: gh (12 n-tiles); z=2: ct, z=3: cs (4 n-tiles)
__global__ void __launch_bounds__(256) gemm_small(const float* __restrict__ dec,
                                                  const float* __restrict__ lasth,
                                                  const float* __restrict__ tgt,
                                                  const float* __restrict__ semb,
                                                  const float* __restrict__ Wih,
                                                  const float* __restrict__ Whh,
                                                  const float* __restrict__ Wtgt,
                                                  const float* __restrict__ Wptr) {
    const int z = blockIdx.z;
    if (z <= 1) {
        gemm64_body(z == 0 ? dec : lasth, z == 0 ? Wih : Whh, 256,
                    z == 0 ? g_gi : g_gh, 768, blockIdx.x * 64, blockIdx.y * 64);
    } else {
        if (blockIdx.y >= 4) return;
        if (z == 2)
            gemm64_body(tgt, Wtgt + H_, 2 * H_, g_ct, 256, blockIdx.x * 64, blockIdx.y * 64);
        else
            gemm64_body(semb, Wptr + 2 * H_, 3 * H_, g_cs, 256, blockIdx.x * 64, blockIdx.y * 64);
    }
}

__global__ void gru_elem(const float* __restrict__ lasth,
                         const float* __restrict__ bih,
                         const float* __restrict__ bhh,
                         float* __restrict__ out_h) {
    const int b = blockIdx.x, t = threadIdx.x;
    const float gir = g_gi[b * 768 + t] + bih[t];
    const float giz = g_gi[b * 768 + t + H_] + bih[t + H_];
    const float gig = g_gi[b * 768 + t + 2 * H_] + bih[t + 2 * H_];
    const float ghr = g_gh[b * 768 + t] + bhh[t];
    const float ghz = g_gh[b * 768 + t + H_] + bhh[t + H_];
    const float ghg = g_gh[b * 768 + t + 2 * H_] + bhh[t + 2 * H_];
    const float r = 1.0f / (1.0f + expf(-(gir + ghr)));
    const float z = 1.0f / (1.0f + expf(-(giz + ghz)));
    const float n = tanhf(gig + r * ghg);
    const float hn = (1.0f - z) * n + z * lasth[b * H_ + t];
    g_hnew[b * H_ + t] = hn;
    out_h[b * H_ + t] = hn;
}

__global__ void __launch_bounds__(256) gemm_ce(const float* __restrict__ Wenc) {
    gemm64_body(g_hnew, Wenc + H_, 2 * H_, g_ce, 256, blockIdx.x * 64, blockIdx.y * 64);
}

// ---------------- big fp16 tensor-core GEMM mainloop (128M x 256N, 512 thr) ----
// K=256 in 8 chunks of 32; 3-stage cp.async for B (256 rows); A fp32 loaded
// per-chunk (coalesced) + in-register fp16 convert; ONE sync per chunk.
#define PADB    80                // smem row stride bytes (64B data + 16 pad)
#define OFF_A   0
#define A_BYTES 10240             // 128 rows
#define OFF_B   10240
#define B_BYTES 20480             // 256 rows
#define STAGEB  30720
#define SMTOT   (3 * STAGEB)      // 92160 bytes dynamic smem

__device__ __forceinline__ void mainloop256(float (&acc)[4][4][4],
                                            const float* __restrict__ X,
                                            int m0, int wrow0,
                                            char* smem, uint32_t sb) {
    const int tid = threadIdx.x;
    const int lane = tid & 31, wid = tid >> 5;
    const int warp_m = wid & 1, warp_n = wid >> 1;   // 2 x 8 warps

    #pragma unroll
    for (int i = 0; i < 4; ++i)
        #pragma unroll
        for (int j = 0; j < 4; ++j)
            #pragma unroll
            for (int k = 0; k < 4; ++k) acc[i][j][k] = 0.f;

    const int arow = tid >> 2;          // 0..127
    const int ac = tid & 3;             // float4 slot (+4 on p=1)

    const uint32_t aOff = (uint32_t)((warp_m * 64 + (lane & 15)) * PADB + (lane >> 4) * 16);
    const uint32_t bOff = (uint32_t)((warp_n * 32 + (lane & 7)) * PADB + ((lane >> 3) & 1) * 16);

    // B fill: 1024 x 16B per chunk; idx = tid + 512q -> row = idx>>2, c = idx&3
    #define FILL_B(stg, kc_)                                                     \
    {                                                                            \
        const int kn_ = (kc_) * 32;                                              \
        _Pragma("unroll")                                                        \
        for (int q = 0; q < 2; ++q) {                                            \
            const int idx = tid + 512 * q;                                       \
            const int row = idx >> 2, c = idx & 3;                               \
            cpa16(sb + (uint32_t)(stg) + OFF_B + (uint32_t)(row * PADB + c * 16),\
                  g_Wh + (size_t)(wrow0 + row) * H_ + kn_ + c * 8);              \
        }                                                                        \
        cpa_commit();                                                            \
    }

    FILL_B(0, 0);
    FILL_B(STAGEB, 1);

    for (int kc = 0; kc < 8; ++kc) {
        const uint32_t so = (uint32_t)((kc % 3) * STAGEB);
        // A(kc): 2 coalesced float4 loads per thread, cvt, store
        {
            const int k0 = kc * 32;
            const float* xr = X + (size_t)(m0 + arow) * H_ + k0;
            #pragma unroll
            for (int p = 0; p < 2; ++p) {
                const int c4 = ac + p * 4;
                const float4 x = *(const float4*)(xr + c4 * 4);
                __half h[4];
                h[0] = __float2half_rn(x.x); h[1] = __float2half_rn(x.y);
                h[2] = __float2half_rn(x.z); h[3] = __float2half_rn(x.w);
                *(uint2*)(smem + so + OFF_A + arow * PADB + c4 * 8) = *(uint2*)h;
            }
        }
        if (kc < 7) asm volatile("cp.async.wait_group 1;" ::: "memory");
        else        asm volatile("cp.async.wait_group 0;" ::: "memory");
        __syncthreads();
        if (kc < 6) {
            const uint32_t s2 = (uint32_t)(((kc + 2) % 3) * STAGEB);
            FILL_B(s2, kc + 2);
        }
        #pragma unroll
        for (int ks = 0; ks < 2; ++ks) {
            const uint32_t kb = ks * 32;
            uint32_t a[4][4], b[4][2];
            #pragma unroll
            for (int i = 0; i < 4; ++i)
                ldsm4(a[i][0], a[i][1], a[i][2], a[i][3],
                      sb + so + OFF_A + aOff + i * (16 * PADB) + kb);
            #pragma unroll
            for (int j = 0; j < 4; ++j)
                ldsm2(b[j][0], b[j][1], sb + so + OFF_B + bOff + j * (8 * PADB) + kb);
            #pragma unroll
            for (int i = 0; i < 4; ++i)
                #pragma unroll
                for (int j = 0; j < 4; ++j)
                    mma16816h(acc[i][j][0], acc[i][j][1], acc[i][j][2], acc[i][j][3],
                              a[i][0], a[i][1], a[i][2], a[i][3], b[j][0], b[j][1]);
        }
    }
    #undef FILL_B
    __syncthreads();   // drain before epilogue reuses smem
}

// ---------------- scores GEMM (one CTA covers a group's full N=256) ------------
__global__ void __launch_bounds__(512, 1) gemm_scores(const float* __restrict__ X,
                                                      const float* __restrict__ v_enc,
                                                      const float* __restrict__ v_tgt) {
    extern __shared__ char smem[];
    const uint32_t sb = s2u(smem);
    const int tid = threadIdx.x;
    const int lane = tid & 31, wid = tid >> 5;
    const int warp_m = wid & 1, warp_n = wid >> 1;
    const int grp = blockIdx.x;               // 0=enc, 1=tgt
    const int m0 = blockIdx.y * 128;

    float acc[4][4][4];
    mainloop256(acc, X, m0, grp * 256, smem, sb);

    float (*red)[8] = (float(*)[8])smem;       // [128][8], aliases stage0
    const int mw = warp_m * 64, nw = warp_n * 32;
    const float* v = (grp == 0) ? v_enc : v_tgt;
    const float* cb = (grp == 0) ? g_ce : g_ct;
    #pragma unroll
    for (int i = 0; i < 4; ++i) {
        #pragma unroll
        for (int r = 0; r < 2; ++r) {
            const int row = mw + i * 16 + r * 8 + (lane >> 2);
            const int b = (m0 + row) / S_;
            const float* cbb = cb + b * H_;
            float p = 0.f;
            #pragma unroll
            for (int j = 0; j < 4; ++j) {
                const int n = nw + j * 8 + (lane & 3) * 2;
                p += __ldg(v + n) * tanhf(acc[i][j][r * 2] + __ldg(cbb + n));
                p += __ldg(v + n + 1) * tanhf(acc[i][j][r * 2 + 1] + __ldg(cbb + n + 1));
            }
            p += __shfl_xor_sync(0xffffffffu, p, 1);
            p += __shfl_xor_sync(0xffffffffu, p, 2);
            if ((lane & 3) == 0) red[row][warp_n] = p;
        }
    }
    __syncthreads();
    if (tid < 128) {
        float s = 0.f;
        #pragma unroll
        for (int w = 0; w < 8; ++w) s += red[tid][w];
        g_scores[grp * M_ + m0 + tid] = s;
    }
}

// ---------------- final GEMM (ptr group, full N) writes probs directly ---------
__global__ void __launch_bounds__(512, 1) gemm_final(const float* __restrict__ X,
                                                     const float* __restrict__ v_ptr,
                                                     float* __restrict__ out) {
    extern __shared__ char smem[];
    const uint32_t sb = s2u(smem);
    const int tid = threadIdx.x;
    const int lane = tid & 31, wid = tid >> 5;
    const int warp_m = wid & 1, warp_n = wid >> 1;
    const int m0 = blockIdx.x * 128;

    float acc[4][4][4];
    mainloop256(acc, X, m0, 512, smem, sb);

    float (*redE)[8] = (float(*)[8])smem;            // [128][8]
    float (*redT)[8] = (float(*)[8])(smem + 4096);   // [128][8]
    const int mw = warp_m * 64, nw = warp_n * 32;
    #pragma unroll
    for (int i = 0; i < 4; ++i) {
        #pragma unroll
        for (int r = 0; r < 2; ++r) {
            const int row = mw + i * 16 + r * 8 + (lane >> 2);
            const int b = (m0 + row) / S_;
            const float* de = g_d + b * H_;
            const float* dt = g_d + B_ * H_ + b * H_;
            float pe = 0.f, pt = 0.f;
            #pragma unroll
            for (int j = 0; j < 4; ++j) {
                const int n = nw + j * 8 + (lane & 3) * 2;
                const float a0 = acc[i][j][r * 2], a1 = acc[i][j][r * 2 + 1];
                const float v0 = __ldg(v_ptr + n), v1 = __ldg(v_ptr + n + 1);
                pe += v0 * tanhf(a0 + __ldg(de + n)) + v1 * tanhf(a1 + __ldg(de + n + 1));
                pt += v0 * tanhf(a0 + __ldg(dt + n)) + v1 * tanhf(a1 + __ldg(dt + n + 1));
            }
            pe += __shfl_xor_sync(0xffffffffu, pe, 1);
            pe += __shfl_xor_sync(0xffffffffu, pe, 2);
            pt += __shfl_xor_sync(0xffffffffu, pt, 1);
            pt += __shfl_xor_sync(0xffffffffu, pt, 2);
            if ((lane & 3) == 0) { redE[row][warp_n] = pe; redT[row][warp_n] = pt; }
        }
    }
    __syncthreads();
    if (tid < 128) {
        float se = 0.f, st = 0.f;
        #pragma unroll
        for (int w = 0; w < 8; ++w) { se += redE[tid][w]; st += redT[tid][w]; }
        out[m0 + tid] = 5.0f * se + st;
    }
}

// ---------------- softmax over S (in place) ------------------------------------
__global__ void softmax_kernel() {
    const int b = blockIdx.x, which = blockIdx.y;
    float* s = g_scores + which * M_ + b * S_;
    const int t = threadIdx.x;
    __shared__ float sred[9];

    float mx = -1e30f;
    for (int i = t; i < S_; i += 256) mx = fmaxf(mx, s[i]);
    #pragma unroll
    for (int o = 16; o > 0; o >>= 1) mx = fmaxf(mx, __shfl_xor_sync(0xffffffffu, mx, o));
    if ((t & 31) == 0) sred[t >> 5] = mx;
    __syncthreads();
    if (t == 0) {
        float m = sred[0];
        for (int w = 1; w < 8; ++w) m = fmaxf(m, sred[w]);
        sred[8] = m;
    }
    __syncthreads();
    mx = sred[8];

    float sm = 0.f;
    for (int i = t; i < S_; i += 256) sm += expf(s[i] - mx);
    #pragma unroll
    for (int o = 16; o > 0; o >>= 1) sm += __shfl_xor_sync(0xffffffffu, sm, o);
    if ((t & 31) == 0) sred[t >> 5] = sm;
    __syncthreads();
    if (t == 0) {
        float m = 0.f;
        for (int w = 0; w < 8; ++w) m += sred[w];
        sred[8] = 1.0f / m;
    }
    __syncthreads();
    const float inv = sred[8];
    for (int i = t; i < S_; i += 256) s[i] = expf(s[i] - mx) * inv;
}

// ---------------- attention contexts: one X pass, both branches ----------------
__global__ void context_kernel(const float* __restrict__ X) {
    const int b = blockIdx.x, chunk = blockIdx.y;  // 20 chunks of 50
    const int t = threadIdx.x;                     // h index
    const float* ae = g_scores + b * S_ + chunk * 50;
    const float* at = g_scores + M_ + b * S_ + chunk * 50;
    const float* x = X + ((size_t)b * S_ + chunk * 50) * H_ + t;
    float ce = 0.f, ct = 0.f;
    #pragma unroll 5
    for (int s = 0; s < 50; ++s) {
        const float xv = x[(size_t)s * H_];
        ce += ae[s] * xv;
        ct += at[s] * xv;
    }
    atomicAdd(&g_ctx[b * H_ + t], ce);
    atomicAdd(&g_ctx[B_ * H_ + b * H_ + t], ct);
}

// ---------------- d vectors -----------------------------------------------------
__global__ void dvec_kernel(const float* __restrict__ Wptr) {
    const int b = blockIdx.x, t = threadIdx.x;
    __shared__ float se[H_], stt[H_];
    se[t] = g_ctx[b * H_ + t];
    stt[t] = g_ctx[B_ * H_ + b * H_ + t];
    __syncthreads();
    float de = g_cs[b * H_ + t], dt = de;
    const float* wr = Wptr + t * (3 * H_) + H_;   // cols [H, 2H)
    #pragma unroll 4
    for (int k = 0; k < H_; ++k) {
        const float w = wr[k];
        de += w * se[k];
        dt += w * stt[k];
    }
    g_d[b * H_ + t] = de;
    g_d[B_ * H_ + b * H_ + t] = dt;
}

// ---------------- launch ---------------------------------------------------------
extern "C" void kernel_launch(void* const* d_in, const int* in_sizes, int n_in,
                              void* d_out, int out_size) {
    const float* x_static = (const float*)d_in[0];
    const float* state_emb = (const float*)d_in[1];
    const float* dec = (const float*)d_in[2];
    const float* tgt = (const float*)d_in[3];
    const float* lasth = (const float*)d_in[4];
    const float* Wih = (const float*)d_in[5];
    const float* Whh = (const float*)d_in[6];
    const float* bih = (const float*)d_in[7];
    const float* bhh = (const float*)d_in[8];
    const float* v_enc = (const float*)d_in[9];
    const float* Wenc = (const float*)d_in[10];
    const float* v_tgt = (const float*)d_in[11];
    const float* Wtgt = (const float*)d_in[12];
    const float* v_ptr = (const float*)d_in[13];
    const float* Wptr = (const float*)d_in[14];

    float* out_probs = (float*)d_out;            // B*S
    float* out_h = (float*)d_out + M_;           // 1*B*H

    // host-side attribute set (idempotent; not a graph node)
    static bool attr_done = false;
    if (!attr_done) {
        cudaFuncSetAttribute(gemm_scores, cudaFuncAttributeMaxDynamicSharedMemorySize, SMTOT);
        cudaFuncSetAttribute(gemm_final, cudaFuncAttributeMaxDynamicSharedMemorySize, SMTOT);
        attr_done = true;
    }

    conv_w<<<96, 256>>>(Wenc, Wtgt, Wptr);
    zero_ctx<<<(2 * B_ * H_ + 255) / 256, 256>>>();
    gemm_small<<<dim3(2, 12, 4), 256>>>(dec, lasth, tgt, state_emb, Wih, Whh, Wtgt, Wptr);
    gru_elem<<<B_, H_>>>(lasth, bih, bhh, out_h);
    gemm_ce<<<dim3(2, 4), 256>>>(Wenc);
    gemm_scores<<<dim3(2, 1000), 512, SMTOT>>>(x_static, v_enc, v_tgt);
    softmax_kernel<<<dim3(B_, 2), 256>>>();
    context_kernel<<<dim3(B_, 20), H_>>>(x_static);
    dvec_kernel<<<B_, H_>>>(Wptr);
    gemm_final<<<1000, 512, SMTOT>>>(x_static, v_ptr, out_probs);
}

// round 16
// speedup vs baseline: 1.0461x; 1.0461x over previous
#include <cuda_runtime.h>
#include <cuda_fp16.h>
#include <math.h>
#include <stdint.h>

#define B_   128
#define S_   1000
#define H_   256
#define M_   (B_ * S_)   // 128000

// ---------------- scratch (__device__ globals; no allocation allowed) ----------
__device__ float g_ce[B_ * H_];
__device__ float g_ct[B_ * H_];
__device__ float g_cs[B_ * H_];
__device__ float g_gi[B_ * 3 * H_];       // dec @ Wih^T
__device__ float g_gh[B_ * 3 * H_];       // lasth @ Whh^T
__device__ float g_hnew[B_ * H_];
__device__ float g_scores[2 * M_];        // softmaxed attention (enc, tgt)
__device__ float g_sp[2][2 * M_];         // raw score partials per n-half
__device__ float g_fp[2][M_];             // final prob partials per n-half
__device__ float g_ctx[2 * B_ * H_];      // enc ctx, tgt ctx
__device__ float g_d[2 * B_ * H_];        // d_e, d_t
// fp16 stacked weights [Wenc1; Wtgt1; Wptr1] cols [0,H)
__device__ __half g_Wh[768 * H_];

// =================== mma.sync / ldmatrix / cp.async helpers ====================
__device__ __forceinline__ uint32_t s2u(const void* p) {
    uint32_t a;
    asm("{ .reg .u64 t; cvta.to.shared.u64 t, %1; cvt.u32.u64 %0, t; }" : "=r"(a) : "l"(p));
    return a;
}
__device__ __forceinline__ void ldsm4(uint32_t& r0, uint32_t& r1, uint32_t& r2, uint32_t& r3,
                                      uint32_t addr) {
    asm volatile("ldmatrix.sync.aligned.m8n8.x4.shared.b16 {%0,%1,%2,%3}, [%4];"
                 : "=r"(r0), "=r"(r1), "=r"(r2), "=r"(r3) : "r"(addr));
}
__device__ __forceinline__ void ldsm2(uint32_t& r0, uint32_t& r1, uint32_t addr) {
    asm volatile("ldmatrix.sync.aligned.m8n8.x2.shared.b16 {%0,%1}, [%2];"
                 : "=r"(r0), "=r"(r1) : "r"(addr));
}
__device__ __forceinline__ void mma16816h(float& d0, float& d1, float& d2, float& d3,
                                          uint32_t a0, uint32_t a1, uint32_t a2, uint32_t a3,
                                          uint32_t b0, uint32_t b1) {
    asm volatile("mma.sync.aligned.m16n8k16.row.col.f32.f16.f16.f32 "
                 "{%0,%1,%2,%3}, {%4,%5,%6,%7}, {%8,%9}, {%0,%1,%2,%3};"
                 : "+f"(d0), "+f"(d1), "+f"(d2), "+f"(d3)
                 : "r"(a0), "r"(a1), "r"(a2), "r"(a3), "r"(b0), "r"(b1));
}
__device__ __forceinline__ void cpa16(uint32_t dst, const void* src) {
    asm volatile("cp.async.cg.shared.global [%0], [%1], 16;" :: "r"(dst), "l"(src));
}
__device__ __forceinline__ void cpa_commit() {
    asm volatile("cp.async.commit_group;" ::: "memory");
}

// ---------------- prepass: weight fp32 -> fp16 + zero ctx (fused) ---------------
__global__ void conv_w(const float* __restrict__ Wenc,
                       const float* __restrict__ Wtgt,
                       const float* __restrict__ Wptr) {
    int g = blockIdx.x * blockDim.x + threadIdx.x;   // 24576 groups of 8
    int row = g >> 5, c8 = g & 31;
    const float* src;
    if (row < 256)      src = Wenc + (size_t)row * (2 * H_) + c8 * 8;
    else if (row < 512) src = Wtgt + (size_t)(row - 256) * (2 * H_) + c8 * 8;
    else                src = Wptr + (size_t)(row - 512) * (3 * H_) + c8 * 8;
    float4 x0 = *(const float4*)src;
    float4 x1 = *(const float4*)(src + 4);
    __half h[8];
    h[0] = __float2half_rn(x0.x); h[1] = __float2half_rn(x0.y);
    h[2] = __float2half_rn(x0.z); h[3] = __float2half_rn(x0.w);
    h[4] = __float2half_rn(x1.x); h[5] = __float2half_rn(x1.y);
    h[6] = __float2half_rn(x1.z); h[7] = __float2half_rn(x1.w);
    *(uint4*)(g_Wh + (size_t)row * H_ + c8 * 8) = *(uint4*)h;
    // fused: zero the ctx accumulators (2*B*H = 65536 floats; 24576 threads)
    for (int i = g; i < 2 * B_ * H_; i += 24576) g_ctx[i] = 0.0f;
}

// ---------------- small fp32 GEMM: C[M,N] = A[M,256] @ W[N,256]^T ---------------
__device__ __forceinline__ void gemm64_body(const float* __restrict__ A,
                                            const float* __restrict__ W, int wstride,
                                            float* __restrict__ C, int ldc,
                                            int m0, int n0) {
    __shared__ float As[32][64];
    __shared__ float Bs[32][64];
    const int tid = threadIdx.x;
    const int lm = tid & 63;
    const int lq = tid >> 6;
    const int tn = tid & 15;
    const int tm = tid >> 4;

    float acc[4][4];
    #pragma unroll
    for (int i = 0; i < 4; ++i)
        #pragma unroll
        for (int j = 0; j < 4; ++j) acc[i][j] = 0.f;

    const float* arow = A + (size_t)(m0 + lm) * 256;
    const float* wrow = W + (size_t)(n0 + lm) * wstride;

    for (int kt = 0; kt < 8; ++kt) {
        const int k0 = kt * 32;
        #pragma unroll
        for (int h = 0; h < 2; ++h) {
            const int kk = (lq + h * 4) * 4;
            float4 xa = *(const float4*)(arow + k0 + kk);
            As[kk + 0][lm] = xa.x; As[kk + 1][lm] = xa.y;
            As[kk + 2][lm] = xa.z; As[kk + 3][lm] = xa.w;
            float4 wa = *(const float4*)(wrow + k0 + kk);
            Bs[kk + 0][lm] = wa.x; Bs[kk + 1][lm] = wa.y;
            Bs[kk + 2][lm] = wa.z; Bs[kk + 3][lm] = wa.w;
        }
        __syncthreads();
        #pragma unroll
        for (int k = 0; k < 32; ++k) {
            float4 a = *(const float4*)&As[k][tm * 4];
            float4 b = *(const float4*)&Bs[k][tn * 4];
            acc[0][0] += a.x * b.x; acc[0][1] += a.x * b.y; acc[0][2] += a.x * b.z; acc[0][3] += a.x * b.w;
            acc[1][0] += a.y * b.x; acc[1][1] += a.y * b.y; acc[1][2] += a.y * b.z; acc[1][3] += a.y * b.w;
            acc[2][0] += a.z * b.x; acc[2][1] += a.z * b.y; acc[2][2] += a.z * b.z; acc[2][3] += a.z * b.w;
            acc[3][0] += a.w * b.x; acc[3][1] += a.w * b.y; acc[3][2] += a.w * b.z; acc[3][3] += a.w * b.w;
        }
        __syncthreads();
    }
    #pragma unroll
    for (int i = 0; i < 4; ++i) {
        float4 o = make_float4(acc[i][0], acc[i][1], acc[i][2], acc[i][3]);
        *(float4*)(C + (size_t)(m0 + tm * 4 + i) * ldc + n0 + tn * 4) = o;
    }
}

// merged small GEMMs: z=0: gi, z=1: gh (12 n-tiles); z=2: ct, z=3: cs (4 n-tiles)
__global__ void __launch_bounds__(256) gemm_small(const float* __restrict__ dec,
                                                  const float* __restrict__ lasth,
                                                  const float* __restrict__ tgt,
                                                  const float* __restrict__ semb,
                                                  const float* __restrict__ Wih,
                                                  const float* __restrict__ Whh,
                                                  const float* __restrict__ Wtgt,
                                                  const float* __restrict__ Wptr) {
    const int z = blockIdx.z;
    if (z <= 1) {
        gemm64_body(z == 0 ? dec : lasth, z == 0 ? Wih : Whh, 256,
                    z == 0 ? g_gi : g_gh, 768, blockIdx.x * 64, blockIdx.y * 64);
    } else {
        if (blockIdx.y >= 4) return;
        if (z == 2)
            gemm64_body(tgt, Wtgt + H_, 2 * H_, g_ct, 256, blockIdx.x * 64, blockIdx.y * 64);
        else
            gemm64_body(semb, Wptr + 2 * H_, 3 * H_, g_cs, 256, blockIdx.x * 64, blockIdx.y * 64);
    }
}

__global__ void gru_elem(const float* __restrict__ lasth,
                         const float* __restrict__ bih,
                         const float* __restrict__ bhh,
                         float* __restrict__ out_h) {
    const int b = blockIdx.x, t = threadIdx.x;
    const float gir = g_gi[b * 768 + t] + bih[t];
    const float giz = g_gi[b * 768 + t + H_] + bih[t + H_];
    const float gig = g_gi[b * 768 + t + 2 * H_] + bih[t + 2 * H_];
    const float ghr = g_gh[b * 768 + t] + bhh[t];
    const float ghz = g_gh[b * 768 + t + H_] + bhh[t + H_];
    const float ghg = g_gh[b * 768 + t + 2 * H_] + bhh[t + 2 * H_];
    const float r = 1.0f / (1.0f + expf(-(gir + ghr)));
    const float z = 1.0f / (1.0f + expf(-(giz + ghz)));
    const float n = tanhf(gig + r * ghg);
    const float hn = (1.0f - z) * n + z * lasth[b * H_ + t];
    g_hnew[b * H_ + t] = hn;
    out_h[b * H_ + t] = hn;
}

__global__ void __launch_bounds__(256) gemm_ce(const float* __restrict__ Wenc) {
    gemm64_body(g_hnew, Wenc + H_, 2 * H_, g_ce, 256, blockIdx.x * 64, blockIdx.y * 64);
}

// ---------------- big fp16 tensor-core GEMM mainloop ----------------------------
// CTA: 128(M) x 128(N), K=256 in 8 chunks of 32, single-pass fp16 mma.
// 3-stage cp.async pipeline for B; A loaded fp32 per-chunk (coalesced) and
// converted in-register. ONE __syncthreads per k-chunk.
#define PADB   80                 // smem row stride bytes (64B data + 16 pad)
#define OFF_A  0
#define OFF_B  10240
#define STAGEB 20480
#define SMTOT  (3 * STAGEB)       // 61440 bytes dynamic smem

__device__ __forceinline__ void mainloop128(float (&acc)[4][4][4],
                                            const float* __restrict__ X,
                                            int m0, int wrow0,
                                            char* smem, uint32_t sb) {
    const int tid = threadIdx.x;
    const int lane = tid & 31, wid = tid >> 5;
    const int warp_m = wid & 1, warp_n = wid >> 1;

    #pragma unroll
    for (int i = 0; i < 4; ++i)
        #pragma unroll
        for (int j = 0; j < 4; ++j)
            #pragma unroll
            for (int k = 0; k < 4; ++k) acc[i][j][k] = 0.f;

    const int arow = tid >> 3;          // 0..31 (+32p)
    const int ac = tid & 7;             // float4 within row

    const uint32_t aOff = (uint32_t)((warp_m * 64 + (lane & 15)) * PADB + (lane >> 4) * 16);
    const uint32_t bOff = (uint32_t)((warp_n * 32 + (lane & 7)) * PADB + ((lane >> 3) & 1) * 16);

    // B fill: idx = tid + 256q -> row = idx>>2, c = idx&3 (2 cpa16 per thread)
    #define FILL_B(stg, kc_)                                                     \
    {                                                                            \
        const int kn_ = (kc_) * 32;                                              \
        _Pragma("unroll")                                                        \
        for (int q = 0; q < 2; ++q) {                                            \
            const int idx = tid + 256 * q;                                       \
            const int row = idx >> 2, c = idx & 3;                               \
            cpa16(sb + (uint32_t)(stg) + OFF_B + (uint32_t)(row * PADB + c * 16),\
                  g_Wh + (size_t)(wrow0 + row) * H_ + kn_ + c * 8);              \
        }                                                                        \
        cpa_commit();                                                            \
    }

    // ---- prologue: B(0), B(1) ----
    FILL_B(0, 0);
    FILL_B(STAGEB, 1);

    for (int kc = 0; kc < 8; ++kc) {
        const uint32_t so = (uint32_t)((kc % 3) * STAGEB);
        // load + convert + store A(kc) -> stage kc%3 (coalesced LDG)
        {
            const int k0 = kc * 32;
            #pragma unroll
            for (int p = 0; p < 4; ++p) {
                const float4 x = *(const float4*)(X + (size_t)(m0 + arow + p * 32) * H_ + k0 + ac * 4);
                __half h[4];
                h[0] = __float2half_rn(x.x); h[1] = __float2half_rn(x.y);
                h[2] = __float2half_rn(x.z); h[3] = __float2half_rn(x.w);
                *(uint2*)(smem + so + OFF_A + (arow + p * 32) * PADB + ac * 8) = *(uint2*)h;
            }
        }
        if (kc < 7) asm volatile("cp.async.wait_group 1;" ::: "memory");
        else        asm volatile("cp.async.wait_group 0;" ::: "memory");
        __syncthreads();
        // issue B(kc+2) AFTER the barrier (stage (kc+2)%3 == (kc-1)%3 is free now)
        if (kc < 6) {
            const uint32_t s2 = (uint32_t)(((kc + 2) % 3) * STAGEB);
            FILL_B(s2, kc + 2);
        }
        // ---- 2 x k16 mma on stage kc%3 ----
        #pragma unroll
        for (int ks = 0; ks < 2; ++ks) {
            const uint32_t kb = ks * 32;
            uint32_t a[4][4], b[4][2];
            #pragma unroll
            for (int i = 0; i < 4; ++i)
                ldsm4(a[i][0], a[i][1], a[i][2], a[i][3],
                      sb + so + OFF_A + aOff + i * (16 * PADB) + kb);
            #pragma unroll
            for (int j = 0; j < 4; ++j)
                ldsm2(b[j][0], b[j][1], sb + so + OFF_B + bOff + j * (8 * PADB) + kb);
            #pragma unroll
            for (int i = 0; i < 4; ++i)
                #pragma unroll
                for (int j = 0; j < 4; ++j)
                    mma16816h(acc[i][j][0], acc[i][j][1], acc[i][j][2], acc[i][j][3],
                              a[i][0], a[i][1], a[i][2], a[i][3], b[j][0], b[j][1]);
        }
        // no end-of-loop sync (3-stage buffering makes it unnecessary)
    }
    #undef FILL_B
    __syncthreads();   // drain before epilogue reuses smem
}

// ---------------- scores GEMM (enc/tgt) with fused v.tanh reduction ------------
__global__ void __launch_bounds__(256, 2) gemm_scores(const float* __restrict__ X,
                                                      const float* __restrict__ v_enc,
                                                      const float* __restrict__ v_tgt) {
    extern __shared__ char smem[];
    const uint32_t sb = s2u(smem);
    const int tid = threadIdx.x;
    const int lane = tid & 31, wid = tid >> 5;
    const int warp_m = wid & 1, warp_n = wid >> 1;
    const int m0 = blockIdx.y * 128;
    const int grp = blockIdx.x >> 1;           // 0=enc, 1=tgt
    const int half = blockIdx.x & 1;
    const int n0 = half * 128;
    const int wrow0 = grp * 256 + n0;

    float acc[4][4][4];
    mainloop128(acc, X, m0, wrow0, smem, sb);

    float (*red)[4] = (float(*)[4])smem;       // alias stage0 (post-drain)
    const int mw = warp_m * 64, nw = warp_n * 32;
    const float* v = (grp == 0) ? v_enc : v_tgt;
    const float* cb = (grp == 0) ? g_ce : g_ct;
    #pragma unroll
    for (int i = 0; i < 4; ++i) {
        #pragma unroll
        for (int r = 0; r < 2; ++r) {
            const int row = mw + i * 16 + r * 8 + (lane >> 2);
            const int b = (m0 + row) / S_;
            const float* cbb = cb + b * H_;
            float p = 0.f;
            #pragma unroll
            for (int j = 0; j < 4; ++j) {
                const int n = n0 + nw + j * 8 + (lane & 3) * 2;
                p += __ldg(v + n) * tanhf(acc[i][j][r * 2] + __ldg(cbb + n));
                p += __ldg(v + n + 1) * tanhf(acc[i][j][r * 2 + 1] + __ldg(cbb + n + 1));
            }
            p += __shfl_xor_sync(0xffffffffu, p, 1);
            p += __shfl_xor_sync(0xffffffffu, p, 2);
            if ((lane & 3) == 0) red[row][warp_n] = p;
        }
    }
    __syncthreads();
    if (tid < 128) {
        const float s = red[tid][0] + red[tid][1] + red[tid][2] + red[tid][3];
        g_sp[half][grp * M_ + m0 + tid] = s;
    }
}

// ---------------- final GEMM (ptr) with fused prob epilogue --------------------
__global__ void __launch_bounds__(256, 2) gemm_final(const float* __restrict__ X,
                                                     const float* __restrict__ v_ptr) {
    extern __shared__ char smem[];
    const uint32_t sb = s2u(smem);
    const int tid = threadIdx.x;
    const int lane = tid & 31, wid = tid >> 5;
    const int warp_m = wid & 1, warp_n = wid >> 1;
    const int m0 = blockIdx.y * 128;
    const int half = blockIdx.x;
    const int n0 = half * 128;
    const int wrow0 = 512 + n0;

    float acc[4][4][4];
    mainloop128(acc, X, m0, wrow0, smem, sb);

    float (*redE)[4] = (float(*)[4])smem;
    float (*redT)[4] = (float(*)[4])(smem + 2048);
    const int mw = warp_m * 64, nw = warp_n * 32;
    #pragma unroll
    for (int i = 0; i < 4; ++i) {
        #pragma unroll
        for (int r = 0; r < 2; ++r) {
            const int row = mw + i * 16 + r * 8 + (lane >> 2);
            const int b = (m0 + row) / S_;
            const float* de = g_d + b * H_;
            const float* dt = g_d + B_ * H_ + b * H_;
            float pe = 0.f, pt = 0.f;
            #pragma unroll
            for (int j = 0; j < 4; ++j) {
                const int n = n0 + nw + j * 8 + (lane & 3) * 2;
                const float a0 = acc[i][j][r * 2], a1 = acc[i][j][r * 2 + 1];
                const float v0 = __ldg(v_ptr + n), v1 = __ldg(v_ptr + n + 1);
                pe += v0 * tanhf(a0 + __ldg(de + n)) + v1 * tanhf(a1 + __ldg(de + n + 1));
                pt += v0 * tanhf(a0 + __ldg(dt + n)) + v1 * tanhf(a1 + __ldg(dt + n + 1));
            }
            pe += __shfl_xor_sync(0xffffffffu, pe, 1);
            pe += __shfl_xor_sync(0xffffffffu, pe, 2);
            pt += __shfl_xor_sync(0xffffffffu, pt, 1);
            pt += __shfl_xor_sync(0xffffffffu, pt, 2);
            if ((lane & 3) == 0) { redE[row][warp_n] = pe; redT[row][warp_n] = pt; }
        }
    }
    __syncthreads();
    if (tid < 128) {
        const float se = redE[tid][0] + redE[tid][1] + redE[tid][2] + redE[tid][3];
        const float st = redT[tid][0] + redT[tid][1] + redT[tid][2] + redT[tid][3];
        g_fp[half][m0 + tid] = 5.0f * se + st;
    }
}

// ---------------- combine final partials ---------------------------------------
__global__ void combine_kernel(float* __restrict__ out) {
    const int i = blockIdx.x * blockDim.x + threadIdx.x;
    out[i] = g_fp[0][i] + g_fp[1][i];
}

// ---------------- softmax over S (sums the two score partials) -----------------
__global__ void softmax_kernel() {
    const int b = blockIdx.x, which = blockIdx.y;
    const float* s0 = g_sp[0] + which * M_ + b * S_;
    const float* s1 = g_sp[1] + which * M_ + b * S_;
    float* so = g_scores + which * M_ + b * S_;
    const int t = threadIdx.x;
    __shared__ float sred[9];
    __shared__ float se_[S_];   // cached exponent arguments

    float mx = -1e30f;
    for (int i = t; i < S_; i += 256) {
        const float sv = s0[i] + s1[i];
        se_[i] = sv;
        mx = fmaxf(mx, sv);
    }
    #pragma unroll
    for (int o = 16; o > 0; o >>= 1) mx = fmaxf(mx, __shfl_xor_sync(0xffffffffu, mx, o));
    if ((t & 31) == 0) sred[t >> 5] = mx;
    __syncthreads();
    if (t == 0) {
        float m = sred[0];
        for (int w = 1; w < 8; ++w) m = fmaxf(m, sred[w]);
        sred[8] = m;
    }
    __syncthreads();
    mx = sred[8];

    float sm = 0.f;
    for (int i = t; i < S_; i += 256) {
        const float e = expf(se_[i] - mx);
        se_[i] = e;
        sm += e;
    }
    #pragma unroll
    for (int o = 16; o > 0; o >>= 1) sm += __shfl_xor_sync(0xffffffffu, sm, o);
    if ((t & 31) == 0) sred[t >> 5] = sm;
    __syncthreads();
    if (t == 0) {
        float m = 0.f;
        for (int w = 0; w < 8; ++w) m += sred[w];
        sred[8] = 1.0f / m;
    }
    __syncthreads();
    const float inv = sred[8];
    for (int i = t; i < S_; i += 256) so[i] = se_[i] * inv;
}

// ---------------- attention contexts: one X pass, both branches ----------------
__global__ void context_kernel(const float* __restrict__ X) {
    const int b = blockIdx.x, chunk = blockIdx.y;  // 20 chunks of 50
    const int t = threadIdx.x;                     // h index
    const float* ae = g_scores + b * S_ + chunk * 50;
    const float* at = g_scores + M_ + b * S_ + chunk * 50;
    const float* x = X + ((size_t)b * S_ + chunk * 50) * H_ + t;
    float ce = 0.f, ct = 0.f;
    #pragma unroll 5
    for (int s = 0; s < 50; ++s) {
        const float xv = x[(size_t)s * H_];
        ce += ae[s] * xv;
        ct += at[s] * xv;
    }
    atomicAdd(&g_ctx[b * H_ + t], ce);
    atomicAdd(&g_ctx[B_ * H_ + b * H_ + t], ct);
}

// ---------------- d vectors -----------------------------------------------------
__global__ void dvec_kernel(const float* __restrict__ Wptr) {
    const int b = blockIdx.x, t = threadIdx.x;
    __shared__ float se[H_], stt[H_];
    se[t] = g_ctx[b * H_ + t];
    stt[t] = g_ctx[B_ * H_ + b * H_ + t];
    __syncthreads();
    float de = g_cs[b * H_ + t], dt = de;
    const float* wr = Wptr + t * (3 * H_) + H_;   // cols [H, 2H)
    #pragma unroll 4
    for (int k = 0; k < H_; ++k) {
        const float w = wr[k];
        de += w * se[k];
        dt += w * stt[k];
    }
    g_d[b * H_ + t] = de;
    g_d[B_ * H_ + b * H_ + t] = dt;
}

// ---------------- launch ---------------------------------------------------------
extern "C" void kernel_launch(void* const* d_in, const int* in_sizes, int n_in,
                              void* d_out, int out_size) {
    const float* x_static = (const float*)d_in[0];
    const float* state_emb = (const float*)d_in[1];
    const float* dec = (const float*)d_in[2];
    const float* tgt = (const float*)d_in[3];
    const float* lasth = (const float*)d_in[4];
    const float* Wih = (const float*)d_in[5];
    const float* Whh = (const float*)d_in[6];
    const float* bih = (const float*)d_in[7];
    const float* bhh = (const float*)d_in[8];
    const float* v_enc = (const float*)d_in[9];
    const float* Wenc = (const float*)d_in[10];
    const float* v_tgt = (const float*)d_in[11];
    const float* Wtgt = (const float*)d_in[12];
    const float* v_ptr = (const float*)d_in[13];
    const float* Wptr = (const float*)d_in[14];

    float* out_probs = (float*)d_out;            // B*S
    float* out_h = (float*)d_out + M_;           // 1*B*H

    // host-side attribute set (idempotent; not a graph node)
    static bool attr_done = false;
    if (!attr_done) {
        cudaFuncSetAttribute(gemm_scores, cudaFuncAttributeMaxDynamicSharedMemorySize, SMTOT);
        cudaFuncSetAttribute(gemm_final, cudaFuncAttributeMaxDynamicSharedMemorySize, SMTOT);
        attr_done = true;
    }

    conv_w<<<96, 256>>>(Wenc, Wtgt, Wptr);   // also zeros g_ctx
    gemm_small<<<dim3(2, 12, 4), 256>>>(dec, lasth, tgt, state_emb, Wih, Whh, Wtgt, Wptr);
    gru_elem<<<B_, H_>>>(lasth, bih, bhh, out_h);
    gemm_ce<<<dim3(2, 4), 256>>>(Wenc);
    gemm_scores<<<dim3(4, 1000), 256, SMTOT>>>(x_static, v_enc, v_tgt);
    softmax_kernel<<<dim3(B_, 2), 256>>>();
    context_kernel<<<dim3(B_, 20), H_>>>(x_static);
    dvec_kernel<<<B_, H_>>>(Wptr);
    gemm_final<<<dim3(2, 1000), 256, SMTOT>>>(x_static, v_ptr);
    combine_kernel<<<M_ / 256, 256>>>(out_probs);
}

// round 17
// speedup vs baseline: 1.0936x; 1.0454x over previous
#include <cuda_runtime.h>
#include <cuda_fp16.h>
#include <math.h>
#include <stdint.h>

#define B_   128
#define S_   1000
#define H_   256
#define M_   (B_ * S_)   // 128000

// ---------------- scratch (__device__ globals; no allocation allowed) ----------
__device__ float g_ce[B_ * H_];
__device__ float g_ct[B_ * H_];
__device__ float g_cs[B_ * H_];
__device__ float g_gi[B_ * 3 * H_];       // dec @ Wih^T
__device__ float g_gh[B_ * 3 * H_];       // lasth @ Whh^T
__device__ float g_hnew[B_ * H_];
__device__ float g_scores[2 * M_];        // softmaxed attention (enc, tgt)
__device__ float g_sp[2][2 * M_];         // raw score partials per n-half
__device__ float g_ctx[2 * B_ * H_];      // enc ctx, tgt ctx
__device__ float g_d[2 * B_ * H_];        // d_e, d_t
// fp16 stacked weights [Wenc1; Wtgt1; Wptr1] cols [0,H)
__device__ __half g_Wh[768 * H_];

// =================== mma.sync / ldmatrix / cp.async helpers ====================
__device__ __forceinline__ uint32_t s2u(const void* p) {
    uint32_t a;
    asm("{ .reg .u64 t; cvta.to.shared.u64 t, %1; cvt.u32.u64 %0, t; }" : "=r"(a) : "l"(p));
    return a;
}
__device__ __forceinline__ void ldsm4(uint32_t& r0, uint32_t& r1, uint32_t& r2, uint32_t& r3,
                                      uint32_t addr) {
    asm volatile("ldmatrix.sync.aligned.m8n8.x4.shared.b16 {%0,%1,%2,%3}, [%4];"
                 : "=r"(r0), "=r"(r1), "=r"(r2), "=r"(r3) : "r"(addr));
}
__device__ __forceinline__ void ldsm2(uint32_t& r0, uint32_t& r1, uint32_t addr) {
    asm volatile("ldmatrix.sync.aligned.m8n8.x2.shared.b16 {%0,%1}, [%2];"
                 : "=r"(r0), "=r"(r1) : "r"(addr));
}
__device__ __forceinline__ void mma16816h(float& d0, float& d1, float& d2, float& d3,
                                          uint32_t a0, uint32_t a1, uint32_t a2, uint32_t a3,
                                          uint32_t b0, uint32_t b1) {
    asm volatile("mma.sync.aligned.m16n8k16.row.col.f32.f16.f16.f32 "
                 "{%0,%1,%2,%3}, {%4,%5,%6,%7}, {%8,%9}, {%0,%1,%2,%3};"
                 : "+f"(d0), "+f"(d1), "+f"(d2), "+f"(d3)
                 : "r"(a0), "r"(a1), "r"(a2), "r"(a3), "r"(b0), "r"(b1));
}
__device__ __forceinline__ void cpa16(uint32_t dst, const void* src) {
    asm volatile("cp.async.cg.shared.global [%0], [%1], 16;" :: "r"(dst), "l"(src));
}
__device__ __forceinline__ void cpa_commit() {
    asm volatile("cp.async.commit_group;" ::: "memory");
}

// ---------------- prepass: weight fp32 -> fp16 + ALL zeroing (fused) -----------
__global__ void conv_w(const float* __restrict__ Wenc,
                       const float* __restrict__ Wtgt,
                       const float* __restrict__ Wptr,
                       float* __restrict__ out) {
    int g = blockIdx.x * blockDim.x + threadIdx.x;   // 24576 threads, groups of 8
    int row = g >> 5, c8 = g & 31;
    const float* src;
    if (row < 256)      src = Wenc + (size_t)row * (2 * H_) + c8 * 8;
    else if (row < 512) src = Wtgt + (size_t)(row - 256) * (2 * H_) + c8 * 8;
    else                src = Wptr + (size_t)(row - 512) * (3 * H_) + c8 * 8;
    float4 x0 = *(const float4*)src;
    float4 x1 = *(const float4*)(src + 4);
    __half h[8];
    h[0] = __float2half_rn(x0.x); h[1] = __float2half_rn(x0.y);
    h[2] = __float2half_rn(x0.z); h[3] = __float2half_rn(x0.w);
    h[4] = __float2half_rn(x1.x); h[5] = __float2half_rn(x1.y);
    h[6] = __float2half_rn(x1.z); h[7] = __float2half_rn(x1.w);
    *(uint4*)(g_Wh + (size_t)row * H_ + c8 * 8) = *(uint4*)h;
    // fused zeroing of all atomic-accumulated buffers
    for (int i = g; i < 2 * B_ * H_; i += 24576) g_ctx[i] = 0.0f;      // 65536
    for (int i = g; i < B_ * 3 * H_; i += 24576) { g_gi[i] = 0.0f; g_gh[i] = 0.0f; }
    for (int i = g; i < B_ * H_; i += 24576) { g_ce[i] = 0.0f; g_ct[i] = 0.0f; g_cs[i] = 0.0f; }
    for (int i = g; i < M_; i += 24576) out[i] = 0.0f;                 // 128000
}

// ------- small fp32 GEMM, HALF-K slice, atomic accumulate -----------------------
// C[m0+.., n0+..] += A[., k0:k0+128] @ W[., k0:k0+128]^T  (64x64 tile, 256 thr)
__device__ __forceinline__ void gemm64_partial(const float* __restrict__ A,
                                               const float* __restrict__ W, int wstride,
                                               float* __restrict__ C, int ldc,
                                               int m0, int n0, int k0g) {
    __shared__ float As[32][64];
    __shared__ float Bs[32][64];
    const int tid = threadIdx.x;
    const int lm = tid & 63;
    const int lq = tid >> 6;
    const int tn = tid & 15;
    const int tm = tid >> 4;

    float acc[4][4];
    #pragma unroll
    for (int i = 0; i < 4; ++i)
        #pragma unroll
        for (int j = 0; j < 4; ++j) acc[i][j] = 0.f;

    const float* arow = A + (size_t)(m0 + lm) * 256 + k0g;
    const float* wrow = W + (size_t)(n0 + lm) * wstride + k0g;

    for (int kt = 0; kt < 4; ++kt) {
        const int k0 = kt * 32;
        #pragma unroll
        for (int h = 0; h < 2; ++h) {
            const int kk = (lq + h * 4) * 4;
            float4 xa = *(const float4*)(arow + k0 + kk);
            As[kk + 0][lm] = xa.x; As[kk + 1][lm] = xa.y;
            As[kk + 2][lm] = xa.z; As[kk + 3][lm] = xa.w;
            float4 wa = *(const float4*)(wrow + k0 + kk);
            Bs[kk + 0][lm] = wa.x; Bs[kk + 1][lm] = wa.y;
            Bs[kk + 2][lm] = wa.z; Bs[kk + 3][lm] = wa.w;
        }
        __syncthreads();
        #pragma unroll
        for (int k = 0; k < 32; ++k) {
            float4 a = *(const float4*)&As[k][tm * 4];
            float4 b = *(const float4*)&Bs[k][tn * 4];
            acc[0][0] += a.x * b.x; acc[0][1] += a.x * b.y; acc[0][2] += a.x * b.z; acc[0][3] += a.x * b.w;
            acc[1][0] += a.y * b.x; acc[1][1] += a.y * b.y; acc[1][2] += a.y * b.z; acc[1][3] += a.y * b.w;
            acc[2][0] += a.z * b.x; acc[2][1] += a.z * b.y; acc[2][2] += a.z * b.z; acc[2][3] += a.z * b.w;
            acc[3][0] += a.w * b.x; acc[3][1] += a.w * b.y; acc[3][2] += a.w * b.z; acc[3][3] += a.w * b.w;
        }
        __syncthreads();
    }
    #pragma unroll
    for (int i = 0; i < 4; ++i) {
        float* crow = C + (size_t)(m0 + tm * 4 + i) * ldc + n0 + tn * 4;
        atomicAdd(crow + 0, acc[i][0]);
        atomicAdd(crow + 1, acc[i][1]);
        atomicAdd(crow + 2, acc[i][2]);
        atomicAdd(crow + 3, acc[i][3]);
    }
}

// merged small GEMMs, split-K x2. grid (2, 12, 8): z -> (mat = z>>1, khalf = z&1)
__global__ void __launch_bounds__(256) gemm_small(const float* __restrict__ dec,
                                                  const float* __restrict__ lasth,
                                                  const float* __restrict__ tgt,
                                                  const float* __restrict__ semb,
                                                  const float* __restrict__ Wih,
                                                  const float* __restrict__ Whh,
                                                  const float* __restrict__ Wtgt,
                                                  const float* __restrict__ Wptr) {
    const int mat = blockIdx.z >> 1;
    const int k0g = (blockIdx.z & 1) * 128;
    if (mat == 0) {
        gemm64_partial(dec, Wih, 256, g_gi, 768, blockIdx.x * 64, blockIdx.y * 64, k0g);
    } else if (mat == 1) {
        gemm64_partial(lasth, Whh, 256, g_gh, 768, blockIdx.x * 64, blockIdx.y * 64, k0g);
    } else {
        if (blockIdx.y >= 4) return;
        if (mat == 2)
            gemm64_partial(tgt, Wtgt + H_, 2 * H_, g_ct, 256, blockIdx.x * 64, blockIdx.y * 64, k0g);
        else
            gemm64_partial(semb, Wptr + 2 * H_, 3 * H_, g_cs, 256, blockIdx.x * 64, blockIdx.y * 64, k0g);
    }
}

__global__ void gru_elem(const float* __restrict__ lasth,
                         const float* __restrict__ bih,
                         const float* __restrict__ bhh,
                         float* __restrict__ out_h) {
    const int b = blockIdx.x, t = threadIdx.x;
    const float gir = g_gi[b * 768 + t] + bih[t];
    const float giz = g_gi[b * 768 + t + H_] + bih[t + H_];
    const float gig = g_gi[b * 768 + t + 2 * H_] + bih[t + 2 * H_];
    const float ghr = g_gh[b * 768 + t] + bhh[t];
    const float ghz = g_gh[b * 768 + t + H_] + bhh[t + H_];
    const float ghg = g_gh[b * 768 + t + 2 * H_] + bhh[t + 2 * H_];
    const float r = 1.0f / (1.0f + expf(-(gir + ghr)));
    const float z = 1.0f / (1.0f + expf(-(giz + ghz)));
    const float n = tanhf(gig + r * ghg);
    const float hn = (1.0f - z) * n + z * lasth[b * H_ + t];
    g_hnew[b * H_ + t] = hn;
    out_h[b * H_ + t] = hn;
}

// ce = hnew @ Wenc[:,H:2H]^T, split-K x2: grid (2, 4, 2)
__global__ void __launch_bounds__(256) gemm_ce(const float* __restrict__ Wenc) {
    gemm64_partial(g_hnew, Wenc + H_, 2 * H_, g_ce, 256,
                   blockIdx.x * 64, blockIdx.y * 64, blockIdx.z * 128);
}

// ---------------- big fp16 tensor-core GEMM mainloop ----------------------------
// CTA: 128(M) x 128(N), K=256 in 8 chunks of 32, single-pass fp16 mma.
// 3-stage cp.async pipeline for B; A loaded fp32 per-chunk (coalesced) and
// converted in-register. ONE __syncthreads per k-chunk.
#define PADB   80                 // smem row stride bytes (64B data + 16 pad)
#define OFF_A  0
#define OFF_B  10240
#define STAGEB 20480
#define SMTOT  (3 * STAGEB)       // 61440 bytes dynamic smem

__device__ __forceinline__ void mainloop128(float (&acc)[4][4][4],
                                            const float* __restrict__ X,
                                            int m0, int wrow0,
                                            char* smem, uint32_t sb) {
    const int tid = threadIdx.x;
    const int lane = tid & 31, wid = tid >> 5;
    const int warp_m = wid & 1, warp_n = wid >> 1;

    #pragma unroll
    for (int i = 0; i < 4; ++i)
        #pragma unroll
        for (int j = 0; j < 4; ++j)
            #pragma unroll
            for (int k = 0; k < 4; ++k) acc[i][j][k] = 0.f;

    const int arow = tid >> 3;          // 0..31 (+32p)
    const int ac = tid & 7;             // float4 within row

    const uint32_t aOff = (uint32_t)((warp_m * 64 + (lane & 15)) * PADB + (lane >> 4) * 16);
    const uint32_t bOff = (uint32_t)((warp_n * 32 + (lane & 7)) * PADB + ((lane >> 3) & 1) * 16);

    // B fill: idx = tid + 256q -> row = idx>>2, c = idx&3 (2 cpa16 per thread)
    #define FILL_B(stg, kc_)                                                     \
    {                                                                            \
        const int kn_ = (kc_) * 32;                                              \
        _Pragma("unroll")                                                        \
        for (int q = 0; q < 2; ++q) {                                            \
            const int idx = tid + 256 * q;                                       \
            const int row = idx >> 2, c = idx & 3;                               \
            cpa16(sb + (uint32_t)(stg) + OFF_B + (uint32_t)(row * PADB + c * 16),\
                  g_Wh + (size_t)(wrow0 + row) * H_ + kn_ + c * 8);              \
        }                                                                        \
        cpa_commit();                                                            \
    }

    // ---- prologue: B(0), B(1) ----
    FILL_B(0, 0);
    FILL_B(STAGEB, 1);

    for (int kc = 0; kc < 8; ++kc) {
        const uint32_t so = (uint32_t)((kc % 3) * STAGEB);
        // load + convert + store A(kc) -> stage kc%3 (coalesced LDG)
        {
            const int k0 = kc * 32;
            #pragma unroll
            for (int p = 0; p < 4; ++p) {
                const float4 x = *(const float4*)(X + (size_t)(m0 + arow + p * 32) * H_ + k0 + ac * 4);
                __half h[4];
                h[0] = __float2half_rn(x.x); h[1] = __float2half_rn(x.y);
                h[2] = __float2half_rn(x.z); h[3] = __float2half_rn(x.w);
                *(uint2*)(smem + so + OFF_A + (arow + p * 32) * PADB + ac * 8) = *(uint2*)h;
            }
        }
        if (kc < 7) asm volatile("cp.async.wait_group 1;" ::: "memory");
        else        asm volatile("cp.async.wait_group 0;" ::: "memory");
        __syncthreads();
        // issue B(kc+2) AFTER the barrier (stage (kc+2)%3 == (kc-1)%3 is free now)
        if (kc < 6) {
            const uint32_t s2 = (uint32_t)(((kc + 2) % 3) * STAGEB);
            FILL_B(s2, kc + 2);
        }
        // ---- 2 x k16 mma on stage kc%3 ----
        #pragma unroll
        for (int ks = 0; ks < 2; ++ks) {
            const uint32_t kb = ks * 32;
            uint32_t a[4][4], b[4][2];
            #pragma unroll
            for (int i = 0; i < 4; ++i)
                ldsm4(a[i][0], a[i][1], a[i][2], a[i][3],
                      sb + so + OFF_A + aOff + i * (16 * PADB) + kb);
            #pragma unroll
            for (int j = 0; j < 4; ++j)
                ldsm2(b[j][0], b[j][1], sb + so + OFF_B + bOff + j * (8 * PADB) + kb);
            #pragma unroll
            for (int i = 0; i < 4; ++i)
                #pragma unroll
                for (int j = 0; j < 4; ++j)
                    mma16816h(acc[i][j][0], acc[i][j][1], acc[i][j][2], acc[i][j][3],
                              a[i][0], a[i][1], a[i][2], a[i][3], b[j][0], b[j][1]);
        }
        // no end-of-loop sync (3-stage buffering makes it unnecessary)
    }
    #undef FILL_B
    __syncthreads();   // drain before epilogue reuses smem
}

// ---------------- scores GEMM (enc/tgt) with fused v.tanh reduction ------------
__global__ void __launch_bounds__(256, 2) gemm_scores(const float* __restrict__ X,
                                                      const float* __restrict__ v_enc,
                                                      const float* __restrict__ v_tgt) {
    extern __shared__ char smem[];
    const uint32_t sb = s2u(smem);
    const int tid = threadIdx.x;
    const int lane = tid & 31, wid = tid >> 5;
    const int warp_m = wid & 1, warp_n = wid >> 1;
    const int m0 = blockIdx.y * 128;
    const int grp = blockIdx.x >> 1;           // 0=enc, 1=tgt
    const int half = blockIdx.x & 1;
    const int n0 = half * 128;
    const int wrow0 = grp * 256 + n0;

    float acc[4][4][4];
    mainloop128(acc, X, m0, wrow0, smem, sb);

    float (*red)[4] = (float(*)[4])smem;       // alias stage0 (post-drain)
    const int mw = warp_m * 64, nw = warp_n * 32;
    const float* v = (grp == 0) ? v_enc : v_tgt;
    const float* cb = (grp == 0) ? g_ce : g_ct;
    #pragma unroll
    for (int i = 0; i < 4; ++i) {
        #pragma unroll
        for (int r = 0; r < 2; ++r) {
            const int row = mw + i * 16 + r * 8 + (lane >> 2);
            const int b = (m0 + row) / S_;
            const float* cbb = cb + b * H_;
            float p = 0.f;
            #pragma unroll
            for (int j = 0; j < 4; ++j) {
                const int n = n0 + nw + j * 8 + (lane & 3) * 2;
                p += __ldg(v + n) * tanhf(acc[i][j][r * 2] + __ldg(cbb + n));
                p += __ldg(v + n + 1) * tanhf(acc[i][j][r * 2 + 1] + __ldg(cbb + n + 1));
            }
            p += __shfl_xor_sync(0xffffffffu, p, 1);
            p += __shfl_xor_sync(0xffffffffu, p, 2);
            if ((lane & 3) == 0) red[row][warp_n] = p;
        }
    }
    __syncthreads();
    if (tid < 128) {
        const float s = red[tid][0] + red[tid][1] + red[tid][2] + red[tid][3];
        g_sp[half][grp * M_ + m0 + tid] = s;
    }
}

// ---------------- final GEMM (ptr): atomic-add probs directly into out ---------
__global__ void __launch_bounds__(256, 2) gemm_final(const float* __restrict__ X,
                                                     const float* __restrict__ v_ptr,
                                                     float* __restrict__ out) {
    extern __shared__ char smem[];
    const uint32_t sb = s2u(smem);
    const int tid = threadIdx.x;
    const int lane = tid & 31, wid = tid >> 5;
    const int warp_m = wid & 1, warp_n = wid >> 1;
    const int m0 = blockIdx.y * 128;
    const int half = blockIdx.x;
    const int n0 = half * 128;
    const int wrow0 = 512 + n0;

    float acc[4][4][4];
    mainloop128(acc, X, m0, wrow0, smem, sb);

    float (*redE)[4] = (float(*)[4])smem;
    float (*redT)[4] = (float(*)[4])(smem + 2048);
    const int mw = warp_m * 64, nw = warp_n * 32;
    #pragma unroll
    for (int i = 0; i < 4; ++i) {
        #pragma unroll
        for (int r = 0; r < 2; ++r) {
            const int row = mw + i * 16 + r * 8 + (lane >> 2);
            const int b = (m0 + row) / S_;
            const float* de = g_d + b * H_;
            const float* dt = g_d + B_ * H_ + b * H_;
            float pe = 0.f, pt = 0.f;
            #pragma unroll
            for (int j = 0; j < 4; ++j) {
                const int n = n0 + nw + j * 8 + (lane & 3) * 2;
                const float a0 = acc[i][j][r * 2], a1 = acc[i][j][r * 2 + 1];
                const float v0 = __ldg(v_ptr + n), v1 = __ldg(v_ptr + n + 1);
                pe += v0 * tanhf(a0 + __ldg(de + n)) + v1 * tanhf(a1 + __ldg(de + n + 1));
                pt += v0 * tanhf(a0 + __ldg(dt + n)) + v1 * tanhf(a1 + __ldg(dt + n + 1));
            }
            pe += __shfl_xor_sync(0xffffffffu, pe, 1);
            pe += __shfl_xor_sync(0xffffffffu, pe, 2);
            pt += __shfl_xor_sync(0xffffffffu, pt, 1);
            pt += __shfl_xor_sync(0xffffffffu, pt, 2);
            if ((lane & 3) == 0) { redE[row][warp_n] = pe; redT[row][warp_n] = pt; }
        }
    }
    __syncthreads();
    if (tid < 128) {
        const float se = redE[tid][0] + redE[tid][1] + redE[tid][2] + redE[tid][3];
        const float st = redT[tid][0] + redT[tid][1] + redT[tid][2] + redT[tid][3];
        atomicAdd(out + m0 + tid, 5.0f * se + st);
    }
}

// ---------------- softmax over S (sums the two score partials) -----------------
__global__ void softmax_kernel() {
    const int b = blockIdx.x, which = blockIdx.y;
    const float* s0 = g_sp[0] + which * M_ + b * S_;
    const float* s1 = g_sp[1] + which * M_ + b * S_;
    float* so = g_scores + which * M_ + b * S_;
    const int t = threadIdx.x;
    __shared__ float sred[9];
    __shared__ float se_[S_];   // cached exponent arguments

    float mx = -1e30f;
    for (int i = t; i < S_; i += 256) {
        const float sv = s0[i] + s1[i];
        se_[i] = sv;
        mx = fmaxf(mx, sv);
    }
    #pragma unroll
    for (int o = 16; o > 0; o >>= 1) mx = fmaxf(mx, __shfl_xor_sync(0xffffffffu, mx, o));
    if ((t & 31) == 0) sred[t >> 5] = mx;
    __syncthreads();
    if (t == 0) {
        float m = sred[0];
        for (int w = 1; w < 8; ++w) m = fmaxf(m, sred[w]);
        sred[8] = m;
    }
    __syncthreads();
    mx = sred[8];

    float sm = 0.f;
    for (int i = t; i < S_; i += 256) {
        const float e = expf(se_[i] - mx);
        se_[i] = e;
        sm += e;
    }
    #pragma unroll
    for (int o = 16; o > 0; o >>= 1) sm += __shfl_xor_sync(0xffffffffu, sm, o);
    if ((t & 31) == 0) sred[t >> 5] = sm;
    __syncthreads();
    if (t == 0) {
        float m = 0.f;
        for (int w = 0; w < 8; ++w) m += sred[w];
        sred[8] = 1.0f / m;
    }
    __syncthreads();
    const float inv = sred[8];
    for (int i = t; i < S_; i += 256) so[i] = se_[i] * inv;
}

// ---------------- attention contexts: one X pass, both branches ----------------
__global__ void context_kernel(const float* __restrict__ X) {
    const int b = blockIdx.x, chunk = blockIdx.y;  // 20 chunks of 50
    const int t = threadIdx.x;                     // h index
    const float* ae = g_scores + b * S_ + chunk * 50;
    const float* at = g_scores + M_ + b * S_ + chunk * 50;
    const float* x = X + ((size_t)b * S_ + chunk * 50) * H_ + t;
    float ce = 0.f, ct = 0.f;
    #pragma unroll 5
    for (int s = 0; s < 50; ++s) {
        const float xv = x[(size_t)s * H_];
        ce += ae[s] * xv;
        ct += at[s] * xv;
    }
    atomicAdd(&g_ctx[b * H_ + t], ce);
    atomicAdd(&g_ctx[B_ * H_ + b * H_ + t], ct);
}

// ---------------- d vectors -----------------------------------------------------
__global__ void dvec_kernel(const float* __restrict__ Wptr) {
    const int b = blockIdx.x, t = threadIdx.x;
    __shared__ float se[H_], stt[H_];
    se[t] = g_ctx[b * H_ + t];
    stt[t] = g_ctx[B_ * H_ + b * H_ + t];
    __syncthreads();
    float de = g_cs[b * H_ + t], dt = de;
    const float* wr = Wptr + t * (3 * H_) + H_;   // cols [H, 2H)
    #pragma unroll 4
    for (int k = 0; k < H_; ++k) {
        const float w = wr[k];
        de += w * se[k];
        dt += w * stt[k];
    }
    g_d[b * H_ + t] = de;
    g_d[B_ * H_ + b * H_ + t] = dt;
}

// ---------------- launch ---------------------------------------------------------
extern "C" void kernel_launch(void* const* d_in, const int* in_sizes, int n_in,
                              void* d_out, int out_size) {
    const float* x_static = (const float*)d_in[0];
    const float* state_emb = (const float*)d_in[1];
    const float* dec = (const float*)d_in[2];
    const float* tgt = (const float*)d_in[3];
    const float* lasth = (const float*)d_in[4];
    const float* Wih = (const float*)d_in[5];
    const float* Whh = (const float*)d_in[6];
    const float* bih = (const float*)d_in[7];
    const float* bhh = (const float*)d_in[8];
    const float* v_enc = (const float*)d_in[9];
    const float* Wenc = (const float*)d_in[10];
    const float* v_tgt = (const float*)d_in[11];
    const float* Wtgt = (const float*)d_in[12];
    const float* v_ptr = (const float*)d_in[13];
    const float* Wptr = (const float*)d_in[14];

    float* out_probs = (float*)d_out;            // B*S
    float* out_h = (float*)d_out + M_;           // 1*B*H

    // host-side attribute set (idempotent; not a graph node)
    static bool attr_done = false;
    if (!attr_done) {
        cudaFuncSetAttribute(gemm_scores, cudaFuncAttributeMaxDynamicSharedMemorySize, SMTOT);
        cudaFuncSetAttribute(gemm_final, cudaFuncAttributeMaxDynamicSharedMemorySize, SMTOT);
        attr_done = true;
    }

    conv_w<<<96, 256>>>(Wenc, Wtgt, Wptr, out_probs);   // converts + zeros everything
    gemm_small<<<dim3(2, 12, 8), 256>>>(dec, lasth, tgt, state_emb, Wih, Whh, Wtgt, Wptr);
    gru_elem<<<B_, H_>>>(lasth, bih, bhh, out_h);
    gemm_ce<<<dim3(2, 4, 2), 256>>>(Wenc);
    gemm_scores<<<dim3(4, 1000), 256, SMTOT>>>(x_static, v_enc, v_tgt);
    softmax_kernel<<<dim3(B_, 2), 256>>>();
    context_kernel<<<dim3(B_, 20), H_>>>(x_static);
    dvec_kernel<<<B_, H_>>>(Wptr);
    gemm_final<<<dim3(2, 1000), 256, SMTOT>>>(x_static, v_ptr, out_probs);
}